// round 1
// baseline (speedup 1.0000x reference)
#include <cuda_runtime.h>

// _QuantumLSTMCell: analytic collapse of the 4-qubit circuit.
// angles = comb @ W^T + b ; z_w = cos(angle_w + th_w)
// E0 = z1 z2 z3 ; E1 = z0 z1 ; E2 = z0 z1 z2 ; E3 = z0 z1 z2 z3
// f,i,o = sigmoid(E), g = tanh(E_u); c' = f*cx + i*g; h' = o*tanh(c')
// out = [h_new (B*4) | c_new (B*4)]

#define THREADS 128
#define D_COLS 256          // x feature dim
#define NKP 130             // 260 / 2 k-pairs
#define NJ 16               // 4 gates * 4 wires

typedef unsigned long long u64;

__device__ __forceinline__ u64 pk(float lo, float hi) {
    u64 r; asm("mov.b64 %0, {%1,%2};" : "=l"(r) : "f"(lo), "f"(hi)); return r;
}
__device__ __forceinline__ void upk(u64 v, float& lo, float& hi) {
    asm("mov.b64 {%0,%1}, %2;" : "=f"(lo), "=f"(hi) : "l"(v));
}
// packed dual-FMA: d.lo += a.lo*b.lo ; d.hi += a.hi*b.hi  (sm_10x f32x2 pipe)
__device__ __forceinline__ void fma2(u64& d, u64 a, u64 b) {
    asm("fma.rn.f32x2 %0, %1, %2, %0;" : "+l"(d) : "l"(a), "l"(b));
}

__device__ __forceinline__ float sigmoidf_(float x) {
    return 1.0f / (1.0f + __expf(-x));
}
__device__ __forceinline__ float tanhf_(float x) {
    return 1.0f - 2.0f / (__expf(2.0f * x) + 1.0f);
}

__device__ __forceinline__ void epilogue(const u64* acc, const float* sphase,
                                         float4 cxv, float4& h4, float4& c4) {
    float z[NJ];
#pragma unroll
    for (int j = 0; j < NJ; j++) {
        float lo, hi; upk(acc[j], lo, hi);
        z[j] = __cosf(lo + hi + sphase[j]);
    }
    float e[NJ];
#pragma unroll
    for (int g = 0; g < 4; g++) {
        float z0 = z[g*4+0], z1 = z[g*4+1], z2 = z[g*4+2], z3 = z[g*4+3];
        float p01 = z0 * z1;
        e[g*4+0] = z1 * z2 * z3;
        e[g*4+1] = p01;
        e[g*4+2] = p01 * z2;
        e[g*4+3] = p01 * z2 * z3;
    }
    float cxa[4] = {cxv.x, cxv.y, cxv.z, cxv.w};
    float hn[4], cn[4];
#pragma unroll
    for (int w = 0; w < 4; w++) {
        float fv = sigmoidf_(e[0*4+w]);
        float iv = sigmoidf_(e[1*4+w]);
        float gv = tanhf_(e[2*4+w]);
        float ov = sigmoidf_(e[3*4+w]);
        float c = fv * cxa[w] + iv * gv;
        cn[w] = c;
        hn[w] = ov * tanhf_(c);
    }
    h4 = make_float4(hn[0], hn[1], hn[2], hn[3]);
    c4 = make_float4(cn[0], cn[1], cn[2], cn[3]);
}

__global__ void __launch_bounds__(THREADS)
qlstm_kernel(const float* __restrict__ x, const float* __restrict__ hx,
             const float* __restrict__ cx,
             const float* __restrict__ Wf, const float* __restrict__ bf,
             const float* __restrict__ Wi, const float* __restrict__ bi,
             const float* __restrict__ Wu, const float* __restrict__ bu,
             const float* __restrict__ Wo, const float* __restrict__ bo,
             const float* __restrict__ tf, const float* __restrict__ ti,
             const float* __restrict__ tu, const float* __restrict__ to,
             float* __restrict__ out, int B)
{
    // packed weights: sw[kpair*16 + j] = (W_j[2k], W_j[2k+1]), j = gate*4 + wire
    __shared__ u64 sw[NKP * NJ];
    __shared__ float sphase[NJ];

    for (int i = threadIdx.x; i < NKP * NJ; i += THREADS) {
        int t = i >> 4, j = i & 15;
        int g = j >> 2, w = j & 3;
        const float* W = (g == 0) ? Wf : (g == 1) ? Wi : (g == 2) ? Wu : Wo;
        const float* row = W + w * 260 + 2 * t;
        sw[i] = pk(row[0], row[1]);
    }
    if (threadIdx.x < NJ) {
        int j = threadIdx.x, g = j >> 2, w = j & 3;
        const float* bb = (g == 0) ? bf : (g == 1) ? bi : (g == 2) ? bu : bo;
        const float* tt = (g == 0) ? tf : (g == 1) ? ti : (g == 2) ? tu : to;
        sphase[j] = bb[w] + tt[w];
    }
    __syncthreads();

    int gt = blockIdx.x * THREADS + threadIdx.x;
    int r0 = gt * 2, r1 = r0 + 1;
    if (r1 >= B) return;

    const float4* xa = (const float4*)x + (size_t)r0 * (D_COLS / 4);
    const float4* xb = (const float4*)x + (size_t)r1 * (D_COLS / 4);

    u64 accA[NJ], accB[NJ];
#pragma unroll
    for (int j = 0; j < NJ; j++) { accA[j] = 0ull; accB[j] = 0ull; }

    float4 a = xa[0], b = xb[0];
#pragma unroll 2
    for (int t4 = 0; t4 < D_COLS / 4; ++t4) {
        int nx = (t4 < D_COLS / 4 - 1) ? t4 + 1 : t4;
        float4 an = xa[nx];
        float4 bn = xb[nx];
        u64 a01 = pk(a.x, a.y), a23 = pk(a.z, a.w);
        u64 b01 = pk(b.x, b.y), b23 = pk(b.z, b.w);
        const u64* w0 = sw + (t4 << 5);       // k-pair 2*t4
        const u64* w1 = w0 + NJ;              // k-pair 2*t4+1
#pragma unroll
        for (int j = 0; j < NJ; j++) {
            u64 w = w0[j];
            fma2(accA[j], a01, w);
            fma2(accB[j], b01, w);
        }
#pragma unroll
        for (int j = 0; j < NJ; j++) {
            u64 w = w1[j];
            fma2(accA[j], a23, w);
            fma2(accB[j], b23, w);
        }
        a = an; b = bn;
    }
    // hx tail: k = 256..259 -> k-pairs 128, 129
    {
        float4 ha = ((const float4*)hx)[r0];
        float4 hb = ((const float4*)hx)[r1];
        u64 a01 = pk(ha.x, ha.y), a23 = pk(ha.z, ha.w);
        u64 b01 = pk(hb.x, hb.y), b23 = pk(hb.z, hb.w);
        const u64* w0 = sw + 128 * NJ;
        const u64* w1 = sw + 129 * NJ;
#pragma unroll
        for (int j = 0; j < NJ; j++) {
            fma2(accA[j], a01, w0[j]);
            fma2(accB[j], b01, w0[j]);
            fma2(accA[j], a23, w1[j]);
            fma2(accB[j], b23, w1[j]);
        }
    }

    float4 cx0 = ((const float4*)cx)[r0];
    float4 cx1 = ((const float4*)cx)[r1];
    float4 h0, c0, h1, c1;
    epilogue(accA, sphase, cx0, h0, c0);
    epilogue(accB, sphase, cx1, h1, c1);

    float4* outh = (float4*)out;
    float4* outc = (float4*)(out + (size_t)B * 4);
    outh[r0] = h0;
    outh[r1] = h1;
    outc[r0] = c0;
    outc[r1] = c1;
}

extern "C" void kernel_launch(void* const* d_in, const int* in_sizes, int n_in,
                              void* d_out, int out_size) {
    const float* x  = (const float*)d_in[0];
    const float* hx = (const float*)d_in[1];
    const float* cx = (const float*)d_in[2];
    const float* Wf = (const float*)d_in[3];
    const float* bf = (const float*)d_in[4];
    const float* Wi = (const float*)d_in[5];
    const float* bi = (const float*)d_in[6];
    const float* Wu = (const float*)d_in[7];
    const float* bu = (const float*)d_in[8];
    const float* Wo = (const float*)d_in[9];
    const float* bo = (const float*)d_in[10];
    const float* tf = (const float*)d_in[11];
    const float* ti = (const float*)d_in[12];
    const float* tu = (const float*)d_in[13];
    const float* to = (const float*)d_in[14];
    float* out = (float*)d_out;

    int B = in_sizes[0] / D_COLS;                 // 131072
    int rows_per_block = THREADS * 2;
    int grid = (B + rows_per_block - 1) / rows_per_block;  // 512

    qlstm_kernel<<<grid, THREADS>>>(x, hx, cx, Wf, bf, Wi, bi, Wu, bu, Wo, bo,
                                    tf, ti, tu, to, out, B);
}